// round 16
// baseline (speedup 1.0000x reference)
#include <cuda_runtime.h>
#include <cuda_fp16.h>
#include <cstdint>

// ---------------- scratch (__device__ globals; no allocs allowed) ------------
__device__ int            g_hq8[1048576];   // hidden quantized int8, packed 4/int32
__device__ int            g_r8 [1048576];   // residual quantized int8, packed
__device__ int            g_wq8[262144];
__device__ int            g_wk8[262144];
__device__ int            g_wv8[262144];
__device__ unsigned short g_Q16[4194304];   // [B*H, S, 64] fp16
__device__ unsigned short g_K16[4194304];
__device__ unsigned short g_V16[4194304];
__device__ unsigned short g_noise[67108864]; // fp16 noise, flat qkt index
__device__ unsigned int   g_absmax[4];      // 0:hidden 1:Wq 2:Wk 3:Wv

// ---------------- absmax / packing ------------------------------------------
__global__ void init_k() {
    if (threadIdx.x < 4) g_absmax[threadIdx.x] = 0u;
}

__global__ void absmax_all_k(const float4* __restrict__ hid, const float4* __restrict__ wq,
                             const float4* __restrict__ wk, const float4* __restrict__ wv) {
    int z = blockIdx.z;
    const float4* x = (z == 0) ? hid : (z == 1) ? wq : (z == 2) ? wk : wv;
    int n4 = (z == 0) ? 1048576 : 262144;
    float m = 0.f;
    for (int i = blockIdx.x * blockDim.x + threadIdx.x; i < n4; i += gridDim.x * blockDim.x) {
        float4 v = x[i];
        m = fmaxf(m, fmaxf(fmaxf(fabsf(v.x), fabsf(v.y)), fmaxf(fabsf(v.z), fabsf(v.w))));
    }
#pragma unroll
    for (int o = 16; o > 0; o >>= 1) m = fmaxf(m, __shfl_xor_sync(0xffffffffu, m, o));
    if ((threadIdx.x & 31) == 0) atomicMax(&g_absmax[z], __float_as_uint(m));
}

__device__ __forceinline__ int pack4i(float a, float b, float c, float d) {
    int ia = (int)a, ib = (int)b, ic = (int)c, id = (int)d;
    return (ia & 0xFF) | ((ib & 0xFF) << 8) | ((ic & 0xFF) << 16) | ((id & 0xFF) << 24);
}

__global__ void pack_all_k(const float4* __restrict__ hid, const float4* __restrict__ wq,
                           const float4* __restrict__ wk, const float4* __restrict__ wv,
                           int* __restrict__ q8, int* __restrict__ r8,
                           int* __restrict__ yq, int* __restrict__ yk, int* __restrict__ yv) {
    int z = blockIdx.z;
    if (z == 0) {
        float s  = fmaxf(__uint_as_float(g_absmax[0]), 1e-8f) / 127.0f;
        float s2 = s / 254.0f;
        for (int i = blockIdx.x * blockDim.x + threadIdx.x; i < 1048576;
             i += gridDim.x * blockDim.x) {
            float4 v = hid[i];
            float qa = fminf(fmaxf(rintf(v.x / s), -127.f), 127.f);
            float qb = fminf(fmaxf(rintf(v.y / s), -127.f), 127.f);
            float qc = fminf(fmaxf(rintf(v.z / s), -127.f), 127.f);
            float qd = fminf(fmaxf(rintf(v.w / s), -127.f), 127.f);
            q8[i] = pack4i(qa, qb, qc, qd);
            float ra = fminf(fmaxf(rintf((v.x - qa * s) / s2), -127.f), 127.f);
            float rb = fminf(fmaxf(rintf((v.y - qb * s) / s2), -127.f), 127.f);
            float rc = fminf(fmaxf(rintf((v.z - qc * s) / s2), -127.f), 127.f);
            float rd = fminf(fmaxf(rintf((v.w - qd * s) / s2), -127.f), 127.f);
            r8[i] = pack4i(ra, rb, rc, rd);
        }
    } else {
        const float4* x = (z == 1) ? wq : (z == 2) ? wk : wv;
        int* y = (z == 1) ? yq : (z == 2) ? yk : yv;
        float s = fmaxf(__uint_as_float(g_absmax[z]), 1e-8f) / 7.0f;
        for (int i = blockIdx.x * blockDim.x + threadIdx.x; i < 262144;
             i += gridDim.x * blockDim.x) {
            float4 v = x[i];
            float a = fminf(fmaxf(rintf(v.x / s), -7.f), 7.f);
            float b = fminf(fmaxf(rintf(v.y / s), -7.f), 7.f);
            float c = fminf(fmaxf(rintf(v.z / s), -7.f), 7.f);
            float d = fminf(fmaxf(rintf(v.w / s), -7.f), 7.f);
            y[i] = pack4i(a, b, c, d);
        }
    }
}

// ---------------- JAX threefry2x32 noise (partitionable, key=(0,42)) --------
__device__ __forceinline__ uint32_t rotl32(uint32_t x, int r) {
    return (x << r) | (x >> (32 - r));
}

__device__ __forceinline__ void threefry2x32(uint32_t c0, uint32_t c1,
                                             uint32_t& o0, uint32_t& o1) {
    const uint32_t k0 = 0u, k1 = 42u, k2 = 0u ^ 42u ^ 0x1BD11BDAu;
    uint32_t x0 = c0 + k0, x1 = c1 + k1;
#define TF_R(r) { x0 += x1; x1 = rotl32(x1, r); x1 ^= x0; }
    TF_R(13) TF_R(15) TF_R(26) TF_R(6)
    x0 += k1; x1 += k2 + 1u;
    TF_R(17) TF_R(29) TF_R(16) TF_R(24)
    x0 += k2; x1 += k0 + 2u;
    TF_R(13) TF_R(15) TF_R(26) TF_R(6)
    x0 += k0; x1 += k1 + 3u;
    TF_R(17) TF_R(29) TF_R(16) TF_R(24)
    x0 += k1; x1 += k2 + 4u;
    TF_R(13) TF_R(15) TF_R(26) TF_R(6)
    x0 += k2; x1 += k0 + 5u;
#undef TF_R
    o0 = x0; o1 = x1;
}

__device__ __forceinline__ float noise_at(unsigned int i) {
    uint32_t o0, o1;
    threefry2x32(0u, i, o0, o1);
    uint32_t bits = o0 ^ o1;
    float f = __uint_as_float((bits >> 9) | 0x3f800000u) - 1.0f;
    const float lo = -0.99999994f;
    float u = fmaxf(lo, fmaf(f, 2.0f, lo));
    float t = fmaf(-u, u, 1.0f);
    float w = -__logf(t);
    float p;
    if (w < 5.0f) {
        w = w - 2.5f;
        p = 2.81022636e-08f;
        p = fmaf(p, w, 3.43273939e-07f);
        p = fmaf(p, w, -3.5233877e-06f);
        p = fmaf(p, w, -4.39150654e-06f);
        p = fmaf(p, w, 0.00021858087f);
        p = fmaf(p, w, -0.00125372503f);
        p = fmaf(p, w, -0.00417768164f);
        p = fmaf(p, w, 0.246640727f);
        p = fmaf(p, w, 1.50140941f);
    } else {
        w = sqrtf(w) - 3.0f;
        p = -0.000200214257f;
        p = fmaf(p, w, 0.000100950558f);
        p = fmaf(p, w, 0.00134934322f);
        p = fmaf(p, w, -0.00367342844f);
        p = fmaf(p, w, 0.00573950773f);
        p = fmaf(p, w, -0.0076224613f);
        p = fmaf(p, w, 0.00943887047f);
        p = fmaf(p, w, 1.00167406f);
        p = fmaf(p, w, 2.83297682f);
    }
    return 1.41421356f * (p * u) * 0.05f;
}

// ---------------- IMMA int8 tensor-core GEMM --------------------------------
__device__ __forceinline__ void imma16832(int& c0, int& c1, int& c2, int& c3,
                                          int a0, int a1, int a2, int a3,
                                          int b0, int b1) {
    asm volatile(
        "mma.sync.aligned.m16n8k32.row.col.s32.s8.s8.s32 "
        "{%0,%1,%2,%3},{%4,%5,%6,%7},{%8,%9},{%0,%1,%2,%3};"
        : "+r"(c0), "+r"(c1), "+r"(c2), "+r"(c3)
        : "r"(a0), "r"(a1), "r"(a2), "r"(a3), "r"(b0), "r"(b1));
}

__device__ __forceinline__ unsigned out_idx(int m, int n) {
    int bb = m >> 10, s = m & 1023, h = n >> 6, dh = n & 63;
    return (unsigned)(((bb * 16 + h) << 16) + (s << 6) + dh);
}

__device__ __forceinline__ uint32_t smem_u32(const void* p) {
    uint32_t a;
    asm("{ .reg .u64 t; cvta.to.shared.u64 t, %1; cvt.u32.u64 %0, t; }" : "=r"(a) : "l"(p));
    return a;
}

__device__ __forceinline__ void cp16(uint32_t d, const void* s) {
    asm volatile("cp.async.cg.shared.global [%0], [%1], 16;" :: "r"(d), "l"(s));
}

__device__ __forceinline__ unsigned h2w(float x, float y) {
    __half2 h = __float22half2_rn(make_float2(x, y));
    return *(unsigned*)&h;
}

// C[m,n] = sum_d A[m,d]*W[n,d]; 128x128 tile, K=1024 int8. cp.async dbuf.
// ISV=0: Q/K (acc1 only -> 2 blocks/SM). ISV=1: V combined + noise generation
// interleaved into the idle ALU pipe (writes g_noise fp16, coalesced).
template <int ISV>
__global__ __launch_bounds__(256, ISV ? 1 : 2) void gemm_imma(
    const int* __restrict__ A8, const int* __restrict__ R8,
    const int* __restrict__ wq8, const int* __restrict__ wk8, const int* __restrict__ wv8,
    unsigned short* __restrict__ Qo, unsigned short* __restrict__ Ko,
    unsigned short* __restrict__ Vo)
{
    extern __shared__ int gsm[];
    int* AsB = gsm;
    int* BsB = gsm + 5120;
    int* RsB = gsm + 10240;

    int z = ISV ? 2 : blockIdx.z;
    const int* W = (z == 0) ? wq8 : (z == 1) ? wk8 : wv8;

    int tid = threadIdx.x;
    int m0 = blockIdx.y * 128, n0 = blockIdx.x * 128;
    int w = tid >> 5, lane = tid & 31, g = lane >> 2, t = lane & 3;
    int wm = (w >> 2) * 64, wn = (w & 3) * 32;

    unsigned gthread = ISV ? ((blockIdx.y * 8u + blockIdx.x) * 256u + (unsigned)tid) : 0u;

    int acc1[4][4][4];
    int acc2[ISV ? 4 : 1][ISV ? 4 : 1][4];
#pragma unroll
    for (int mi = 0; mi < 4; mi++)
#pragma unroll
        for (int ni = 0; ni < 4; ni++)
#pragma unroll
            for (int e = 0; e < 4; e++) acc1[mi][ni][e] = 0;
    if (ISV) {
#pragma unroll
        for (int mi = 0; mi < 4; mi++)
#pragma unroll
            for (int ni = 0; ni < 4; ni++)
#pragma unroll
                for (int e = 0; e < 4; e++) acc2[mi][ni][e] = 0;
    }

    int srow = tid >> 1, shalf = (tid & 1) * 8;
    const int* Ag = A8 + (m0 + srow) * 256 + shalf;
    const int* Rg = R8 + (m0 + srow) * 256 + shalf;
    const int* Wg = W  + (n0 + srow) * 256 + shalf;
    int sboff = (srow * 20 + shalf) * 4;

    uint32_t sA = smem_u32(AsB), sB = smem_u32(BsB), sR = smem_u32(RsB);

    {
        cp16(sA + sboff, Ag);      cp16(sA + sboff + 16, Ag + 4);
        cp16(sB + sboff, Wg);      cp16(sB + sboff + 16, Wg + 4);
        if (ISV) { cp16(sR + sboff, Rg); cp16(sR + sboff + 16, Rg + 4); }
        asm volatile("cp.async.commit_group;");
    }

    for (int ks = 0; ks < 16; ks++) {
        int cur = ks & 1, nxt = cur ^ 1;
        if (ks < 15) {
            uint32_t boff = (uint32_t)nxt * 10240u + (uint32_t)sboff;
            const int* a = Ag + (ks + 1) * 16;
            const int* b = Wg + (ks + 1) * 16;
            cp16(sA + boff, a); cp16(sA + boff + 16, a + 4);
            cp16(sB + boff, b); cp16(sB + boff + 16, b + 4);
            if (ISV) {
                const int* r = Rg + (ks + 1) * 16;
                cp16(sR + boff, r); cp16(sR + boff + 16, r + 4);
            }
            asm volatile("cp.async.commit_group;");
            asm volatile("cp.async.wait_group 1;");
        } else {
            asm volatile("cp.async.wait_group 0;");
        }
        __syncthreads();

        const int* Asw = AsB + cur * 2560;
        const int* Bsw = BsB + cur * 2560;
        const int* Rsw = RsB + cur * 2560;

#pragma unroll
        for (int kk = 0; kk < 2; kk++) {
            int bb0[4], bb1[4];
#pragma unroll
            for (int ni = 0; ni < 4; ni++) {
                int brow = (wn + ni * 8 + g) * 20 + kk * 8;
                bb0[ni] = Bsw[brow + t];
                bb1[ni] = Bsw[brow + 4 + t];
            }
#pragma unroll
            for (int mi = 0; mi < 4; mi++) {
                int ar0 = (wm + mi * 16 + g) * 20 + kk * 8;
                int ar1 = (wm + mi * 16 + 8 + g) * 20 + kk * 8;
                int a0 = Asw[ar0 + t], a1 = Asw[ar1 + t];
                int a2 = Asw[ar0 + 4 + t], a3 = Asw[ar1 + 4 + t];
#pragma unroll
                for (int ni = 0; ni < 4; ni++)
                    imma16832(acc1[mi][ni][0], acc1[mi][ni][1], acc1[mi][ni][2], acc1[mi][ni][3],
                              a0, a1, a2, a3, bb0[ni], bb1[ni]);
                if (ISV) {
                    int r0 = Rsw[ar0 + t], r1 = Rsw[ar1 + t];
                    int r2 = Rsw[ar0 + 4 + t], r3 = Rsw[ar1 + 4 + t];
#pragma unroll
                    for (int ni = 0; ni < 4; ni++)
                        imma16832(acc2[mi][ni][0], acc2[mi][ni][1], acc2[mi][ni][2], acc2[mi][ni][3],
                                  r0, r1, r2, r3, bb0[ni], bb1[ni]);
                }
            }
        }

        // interleaved noise generation on the idle ALU pipe (ISV only):
        // 32 fp16 pairs / thread / slab -> 512 pairs total = 1024 values.
        if (ISV) {
            unsigned* nz = (unsigned*)g_noise;
#pragma unroll 2
            for (int p = 0; p < 32; p++) {
                unsigned u = (unsigned)(ks * 32 + p) * 65536u + gthread;
                nz[u] = h2w(noise_at(2u * u), noise_at(2u * u + 1u));
            }
        }
        __syncthreads();
    }

    float sa = fmaxf(__uint_as_float(g_absmax[0]), 1e-8f) / 127.0f;
    float sw = fmaxf(__uint_as_float(g_absmax[z + 1]), 1e-8f) / 7.0f;
    float k1 = sa * sw;
    float k2 = (sa / 254.0f) * sw;
    unsigned short* O = (z == 0) ? Qo : (z == 1) ? Ko : Vo;

#pragma unroll
    for (int mi = 0; mi < 4; mi++) {
        int r0 = m0 + wm + mi * 16 + g;
        int r1 = r0 + 8;
#pragma unroll
        for (int ni = 0; ni < 4; ni++) {
            int c0 = n0 + wn + ni * 8 + 2 * t;
            float v00, v01, v10, v11;
            if (!ISV) {
                v00 = (float)acc1[mi][ni][0] * k1;
                v01 = (float)acc1[mi][ni][1] * k1;
                v10 = (float)acc1[mi][ni][2] * k1;
                v11 = (float)acc1[mi][ni][3] * k1;
            } else {
                v00 = fmaf((float)acc2[mi][ni][0], k2, (float)acc1[mi][ni][0] * k1);
                v01 = fmaf((float)acc2[mi][ni][1], k2, (float)acc1[mi][ni][1] * k1);
                v10 = fmaf((float)acc2[mi][ni][2], k2, (float)acc1[mi][ni][2] * k1);
                v11 = fmaf((float)acc2[mi][ni][3], k2, (float)acc1[mi][ni][3] * k1);
            }
            *(unsigned*)&O[out_idx(r0, c0)] = h2w(v00, v01);
            *(unsigned*)&O[out_idx(r1, c0)] = h2w(v10, v11);
        }
    }
}

// ---------------- HMMA helpers ----------------------------------------------
__device__ __forceinline__ void mma16816(float& c0, float& c1, float& c2, float& c3,
                                         unsigned a0, unsigned a1, unsigned a2, unsigned a3,
                                         unsigned b0, unsigned b1) {
    asm volatile(
        "mma.sync.aligned.m16n8k16.row.col.f32.f16.f16.f32 "
        "{%0,%1,%2,%3},{%4,%5,%6,%7},{%8,%9},{%0,%1,%2,%3};"
        : "+f"(c0), "+f"(c1), "+f"(c2), "+f"(c3)
        : "r"(a0), "r"(a1), "r"(a2), "r"(a3), "r"(b0), "r"(b1));
}

// ---------------- fused flash attention (HMMA fp16, precomputed noise) -------
#define PLANEW 2304   // 64 rows * 36 words
__global__ __launch_bounds__(128, 4) void attn_k(
    const unsigned short* __restrict__ Q16, const unsigned short* __restrict__ K16,
    const unsigned short* __restrict__ V16, const float* __restrict__ mask,
    float* __restrict__ out)
{
    extern __shared__ unsigned smw[];
    unsigned* qh_s = smw;
    unsigned* kh_s = smw + PLANEW;
    unsigned* vt_s = smw + 2 * PLANEW;
    float* Ms = (float*)(smw + 3 * PLANEW);

    int bh = blockIdx.x, qt = blockIdx.y;
    int b = bh >> 4, h = bh & 15;
    int tid = threadIdx.x, w = tid >> 5, lane = tid & 31;
    int g = lane >> 2, t = lane & 3;

    const unsigned* Qw = (const unsigned*)(Q16 + (size_t)(bh * 1024 + qt * 64) * 64);
    for (int i = tid; i < 2048; i += 128) {
        int q = i >> 5, dp = i & 31;
        qh_s[q * 36 + dp] = Qw[q * 32 + dp];
    }
    __syncthreads();

    unsigned qh[4][4];
    int qr = w * 16 + g;
#pragma unroll
    for (int c = 0; c < 4; c++) {
        int wp = c * 8 + t;
        qh[c][0] = qh_s[qr * 36 + wp];
        qh[c][1] = qh_s[(qr + 8) * 36 + wp];
        qh[c][2] = qh_s[qr * 36 + wp + 4];
        qh[c][3] = qh_s[(qr + 8) * 36 + wp + 4];
    }

    float m0r = -1e30f, m1r = -1e30f, l0r = 0.f, l1r = 0.f;
    float O[8][4];
#pragma unroll
    for (int n = 0; n < 8; n++)
#pragma unroll
        for (int e = 0; e < 4; e++) O[n][e] = 0.f;

    const float* maskb = mask + (b << 10);
    unsigned base0 = ((unsigned)bh << 20) | ((unsigned)(qt * 64 + qr) << 10);
    const unsigned* nzw = (const unsigned*)g_noise;

    for (int kt = 0; kt < 16; kt++) {
        __syncthreads();
        const unsigned* Kw = (const unsigned*)(K16 + (size_t)(bh * 1024 + kt * 64) * 64);
        const unsigned short* Vg = V16 + (size_t)(bh * 1024 + kt * 64) * 64;
        for (int i = tid; i < 2048; i += 128) {
            int k = i >> 5, dp = i & 31;
            kh_s[k * 36 + dp] = Kw[k * 32 + dp];
            int d = i & 63, kp = i >> 6;
            unsigned v0 = Vg[(2 * kp) * 64 + d];
            unsigned v1 = Vg[(2 * kp + 1) * 64 + d];
            int col = kp ^ ((d >> 3) & 3);
            vt_s[d * 36 + col] = v0 | (v1 << 16);
        }
        if (tid < 64) Ms[tid] = maskb[kt * 64 + tid];
        __syncthreads();

        // ---- preload noise for this ktile (half2 words)
        unsigned nw0[8], nw1[8];
#pragma unroll
        for (int j = 0; j < 8; j++) {
            unsigned kc = (unsigned)(kt * 64 + j * 8 + 2 * t);
            nw0[j] = nzw[(base0 + kc) >> 1];
            nw1[j] = nzw[(base0 + (8u << 10) + kc) >> 1];
        }

        // ---- S = Q K^T (single fp16 term)
        float S[8][4];
#pragma unroll
        for (int n = 0; n < 8; n++)
#pragma unroll
            for (int e = 0; e < 4; e++) S[n][e] = 0.f;

#pragma unroll
        for (int j = 0; j < 8; j++) {
            int krow = j * 8 + g;
#pragma unroll
            for (int c = 0; c < 4; c++) {
                int wp = c * 8 + t;
                unsigned bh0 = kh_s[krow * 36 + wp];
                unsigned bh1 = kh_s[krow * 36 + wp + 4];
                mma16816(S[j][0], S[j][1], S[j][2], S[j][3],
                         qh[c][0], qh[c][1], qh[c][2], qh[c][3], bh0, bh1);
            }
        }

        // ---- scale + noise + mask
#pragma unroll
        for (int j = 0; j < 8; j++) {
            float mv0 = Ms[j * 8 + 2 * t], mv1 = Ms[j * 8 + 2 * t + 1];
            float2 nA = __half22float2(*(const __half2*)&nw0[j]);
            float2 nB = __half22float2(*(const __half2*)&nw1[j]);
            S[j][0] = fmaf(S[j][0], 0.125f, nA.x + mv0);
            S[j][1] = fmaf(S[j][1], 0.125f, nA.y + mv1);
            S[j][2] = fmaf(S[j][2], 0.125f, nB.x + mv0);
            S[j][3] = fmaf(S[j][3], 0.125f, nB.y + mv1);
        }

        // ---- online softmax
        float tm0 = -1e30f, tm1 = -1e30f;
#pragma unroll
        for (int j = 0; j < 8; j++) {
            tm0 = fmaxf(tm0, fmaxf(S[j][0], S[j][1]));
            tm1 = fmaxf(tm1, fmaxf(S[j][2], S[j][3]));
        }
        tm0 = fmaxf(tm0, __shfl_xor_sync(0xffffffffu, tm0, 1));
        tm0 = fmaxf(tm0, __shfl_xor_sync(0xffffffffu, tm0, 2));
        tm1 = fmaxf(tm1, __shfl_xor_sync(0xffffffffu, tm1, 1));
        tm1 = fmaxf(tm1, __shfl_xor_sync(0xffffffffu, tm1, 2));
        float mn0 = fmaxf(m0r, tm0), mn1 = fmaxf(m1r, tm1);
        float cor0 = __expf(m0r - mn0), cor1 = __expf(m1r - mn1);
        m0r = mn0; m1r = mn1;
        float ps0 = 0.f, ps1 = 0.f;
#pragma unroll
        for (int j = 0; j < 8; j++) {
            S[j][0] = __expf(S[j][0] - mn0); S[j][1] = __expf(S[j][1] - mn0);
            S[j][2] = __expf(S[j][2] - mn1); S[j][3] = __expf(S[j][3] - mn1);
            ps0 += S[j][0] + S[j][1];
            ps1 += S[j][2] + S[j][3];
        }
        ps0 += __shfl_xor_sync(0xffffffffu, ps0, 1);
        ps0 += __shfl_xor_sync(0xffffffffu, ps0, 2);
        ps1 += __shfl_xor_sync(0xffffffffu, ps1, 1);
        ps1 += __shfl_xor_sync(0xffffffffu, ps1, 2);
        l0r = l0r * cor0 + ps0;
        l1r = l1r * cor1 + ps1;
#pragma unroll
        for (int n = 0; n < 8; n++) {
            O[n][0] *= cor0; O[n][1] *= cor0;
            O[n][2] *= cor1; O[n][3] *= cor1;
        }

        // ---- P -> fp16 A-frags
        unsigned ph[4][4];
#pragma unroll
        for (int c = 0; c < 4; c++) {
            ph[c][0] = h2w(S[2 * c][0],     S[2 * c][1]);
            ph[c][1] = h2w(S[2 * c][2],     S[2 * c][3]);
            ph[c][2] = h2w(S[2 * c + 1][0], S[2 * c + 1][1]);
            ph[c][3] = h2w(S[2 * c + 1][2], S[2 * c + 1][3]);
        }

        // ---- O += P V (single fp16 term; swizzled V^T plane)
#pragma unroll
        for (int n = 0; n < 8; n++) {
            int vrow = n * 8 + g;
            int vs = n & 3;
#pragma unroll
            for (int c = 0; c < 4; c++) {
                int wp0 = (c * 8 + t) ^ vs;
                int wp1 = (c * 8 + 4 + t) ^ vs;
                unsigned bh0 = vt_s[vrow * 36 + wp0];
                unsigned bh1 = vt_s[vrow * 36 + wp1];
                mma16816(O[n][0], O[n][1], O[n][2], O[n][3],
                         ph[c][0], ph[c][1], ph[c][2], ph[c][3], bh0, bh1);
            }
        }
    }

    float inv0 = 1.0f / l0r, inv1 = 1.0f / l1r;
    int q0 = qt * 64 + qr;
    float* o0 = out + ((size_t)((b << 10) + q0)) * 1024 + (h << 6);
    float* o1 = out + ((size_t)((b << 10) + q0 + 8)) * 1024 + (h << 6);
#pragma unroll
    for (int n = 0; n < 8; n++) {
        int dh = n * 8 + 2 * t;
        *(float2*)(o0 + dh) = make_float2(O[n][0] * inv0, O[n][1] * inv0);
        *(float2*)(o1 + dh) = make_float2(O[n][2] * inv1, O[n][3] * inv1);
    }
}

// ---------------- launch -----------------------------------------------------
extern "C" void kernel_launch(void* const* d_in, const int* in_sizes, int n_in,
                              void* d_out, int out_size) {
    const float* hidden = (const float*)d_in[0];
    const float* mask   = (const float*)d_in[1];
    const float* Wq     = (const float*)d_in[2];
    const float* Wk     = (const float*)d_in[3];
    const float* Wv     = (const float*)d_in[4];
    float* out = (float*)d_out;

    int *hq8, *r8, *wq8, *wk8, *wv8;
    unsigned short *Qp, *Kp, *Vp;
    cudaGetSymbolAddress((void**)&hq8, g_hq8);
    cudaGetSymbolAddress((void**)&r8,  g_r8);
    cudaGetSymbolAddress((void**)&wq8, g_wq8);
    cudaGetSymbolAddress((void**)&wk8, g_wk8);
    cudaGetSymbolAddress((void**)&wv8, g_wv8);
    cudaGetSymbolAddress((void**)&Qp,  g_Q16);
    cudaGetSymbolAddress((void**)&Kp,  g_K16);
    cudaGetSymbolAddress((void**)&Vp,  g_V16);

    init_k<<<1, 32>>>();
    absmax_all_k<<<dim3(128, 1, 4), 256>>>((const float4*)hidden, (const float4*)Wq,
                                           (const float4*)Wk, (const float4*)Wv);
    pack_all_k<<<dim3(256, 1, 4), 256>>>((const float4*)hidden, (const float4*)Wq,
                                         (const float4*)Wk, (const float4*)Wv,
                                         hq8, r8, wq8, wk8, wv8);

    cudaFuncSetAttribute(gemm_imma<0>, cudaFuncAttributeMaxDynamicSharedMemorySize, 40960);
    cudaFuncSetAttribute(gemm_imma<1>, cudaFuncAttributeMaxDynamicSharedMemorySize, 61440);
    gemm_imma<0><<<dim3(8, 32, 2), 256, 40960>>>(hq8, r8, wq8, wk8, wv8, Qp, Kp, Vp);
    gemm_imma<1><<<dim3(8, 32, 1), 256, 61440>>>(hq8, r8, wq8, wk8, wv8, Qp, Kp, Vp);

    int smem_bytes = 3 * PLANEW * 4 + 64 * 4;
    cudaFuncSetAttribute(attn_k, cudaFuncAttributeMaxDynamicSharedMemorySize, smem_bytes);
    attn_k<<<dim3(64, 16), 128, smem_bytes>>>(Qp, Kp, Vp, mask, out);
}

// round 17
// speedup vs baseline: 1.1745x; 1.1745x over previous
#include <cuda_runtime.h>
#include <cuda_fp16.h>
#include <cstdint>

// ---------------- scratch (__device__ globals; no allocs allowed) ------------
__device__ int            g_hq8[1048576];   // hidden quantized int8, packed 4/int32
__device__ int            g_r8 [1048576];   // residual quantized int8, packed
__device__ int            g_wq8[262144];
__device__ int            g_wk8[262144];
__device__ int            g_wv8[262144];
__device__ int            g_vp [4194304];   // V main-term int32 partial (head-split)
__device__ unsigned short g_Q16[4194304];   // [B*H, S, 64] fp16
__device__ unsigned short g_K16[4194304];
__device__ unsigned short g_V16[4194304];
__device__ unsigned int   g_absmax[4];      // 0:hidden 1:Wq 2:Wk 3:Wv

// ---------------- absmax / packing ------------------------------------------
__global__ void init_k() {
    if (threadIdx.x < 4) g_absmax[threadIdx.x] = 0u;
}

__global__ void absmax_all_k(const float4* __restrict__ hid, const float4* __restrict__ wq,
                             const float4* __restrict__ wk, const float4* __restrict__ wv) {
    int z = blockIdx.z;
    const float4* x = (z == 0) ? hid : (z == 1) ? wq : (z == 2) ? wk : wv;
    int n4 = (z == 0) ? 1048576 : 262144;
    float m = 0.f;
    for (int i = blockIdx.x * blockDim.x + threadIdx.x; i < n4; i += gridDim.x * blockDim.x) {
        float4 v = x[i];
        m = fmaxf(m, fmaxf(fmaxf(fabsf(v.x), fabsf(v.y)), fmaxf(fabsf(v.z), fabsf(v.w))));
    }
#pragma unroll
    for (int o = 16; o > 0; o >>= 1) m = fmaxf(m, __shfl_xor_sync(0xffffffffu, m, o));
    if ((threadIdx.x & 31) == 0) atomicMax(&g_absmax[z], __float_as_uint(m));
}

__device__ __forceinline__ int pack4i(float a, float b, float c, float d) {
    int ia = (int)a, ib = (int)b, ic = (int)c, id = (int)d;
    return (ia & 0xFF) | ((ib & 0xFF) << 8) | ((ic & 0xFF) << 16) | ((id & 0xFF) << 24);
}

__global__ void pack_all_k(const float4* __restrict__ hid, const float4* __restrict__ wq,
                           const float4* __restrict__ wk, const float4* __restrict__ wv,
                           int* __restrict__ q8, int* __restrict__ r8,
                           int* __restrict__ yq, int* __restrict__ yk, int* __restrict__ yv) {
    int z = blockIdx.z;
    if (z == 0) {
        float s  = fmaxf(__uint_as_float(g_absmax[0]), 1e-8f) / 127.0f;
        float s2 = s / 254.0f;
        for (int i = blockIdx.x * blockDim.x + threadIdx.x; i < 1048576;
             i += gridDim.x * blockDim.x) {
            float4 v = hid[i];
            float qa = fminf(fmaxf(rintf(v.x / s), -127.f), 127.f);
            float qb = fminf(fmaxf(rintf(v.y / s), -127.f), 127.f);
            float qc = fminf(fmaxf(rintf(v.z / s), -127.f), 127.f);
            float qd = fminf(fmaxf(rintf(v.w / s), -127.f), 127.f);
            q8[i] = pack4i(qa, qb, qc, qd);
            float ra = fminf(fmaxf(rintf((v.x - qa * s) / s2), -127.f), 127.f);
            float rb = fminf(fmaxf(rintf((v.y - qb * s) / s2), -127.f), 127.f);
            float rc = fminf(fmaxf(rintf((v.z - qc * s) / s2), -127.f), 127.f);
            float rd = fminf(fmaxf(rintf((v.w - qd * s) / s2), -127.f), 127.f);
            r8[i] = pack4i(ra, rb, rc, rd);
        }
    } else {
        const float4* x = (z == 1) ? wq : (z == 2) ? wk : wv;
        int* y = (z == 1) ? yq : (z == 2) ? yk : yv;
        float s = fmaxf(__uint_as_float(g_absmax[z]), 1e-8f) / 7.0f;
        for (int i = blockIdx.x * blockDim.x + threadIdx.x; i < 262144;
             i += gridDim.x * blockDim.x) {
            float4 v = x[i];
            float a = fminf(fmaxf(rintf(v.x / s), -7.f), 7.f);
            float b = fminf(fmaxf(rintf(v.y / s), -7.f), 7.f);
            float c = fminf(fmaxf(rintf(v.z / s), -7.f), 7.f);
            float d = fminf(fmaxf(rintf(v.w / s), -7.f), 7.f);
            y[i] = pack4i(a, b, c, d);
        }
    }
}

// ---------------- IMMA int8 tensor-core GEMM --------------------------------
__device__ __forceinline__ void imma16832(int& c0, int& c1, int& c2, int& c3,
                                          int a0, int a1, int a2, int a3,
                                          int b0, int b1) {
    asm volatile(
        "mma.sync.aligned.m16n8k32.row.col.s32.s8.s8.s32 "
        "{%0,%1,%2,%3},{%4,%5,%6,%7},{%8,%9},{%0,%1,%2,%3};"
        : "+r"(c0), "+r"(c1), "+r"(c2), "+r"(c3)
        : "r"(a0), "r"(a1), "r"(a2), "r"(a3), "r"(b0), "r"(b1));
}

__device__ __forceinline__ unsigned out_idx(int m, int n) {
    int bb = m >> 10, s = m & 1023, h = n >> 6, dh = n & 63;
    return (unsigned)(((bb * 16 + h) << 16) + (s << 6) + dh);
}

__device__ __forceinline__ uint32_t smem_u32(const void* p) {
    uint32_t a;
    asm("{ .reg .u64 t; cvta.to.shared.u64 t, %1; cvt.u32.u64 %0, t; }" : "=r"(a) : "l"(p));
    return a;
}

__device__ __forceinline__ void cp16(uint32_t d, const void* s) {
    asm volatile("cp.async.cg.shared.global [%0], [%1], 16;" :: "r"(d), "l"(s));
}

__device__ __forceinline__ unsigned h2w(float x, float y) {
    __half2 h = __float22half2_rn(make_float2(x, y));
    return *(unsigned*)&h;
}

// Single-accumulator 128x128 IMMA GEMM core, cp.async double-buffered.
// PASS=0 (launch 1, grid.z=3): z=0 Q->fp16, z=1 K->fp16, z=2 V-main -> int32 scratch.
// PASS=1 (launch 2): V-res = r8@Wv; epilogue combines with scratch -> fp16 V.
template <int PASS>
__global__ __launch_bounds__(256, 2) void gemm_imma(
    const int* __restrict__ A8,
    const int* __restrict__ wq8, const int* __restrict__ wk8, const int* __restrict__ wv8,
    unsigned short* __restrict__ Qo, unsigned short* __restrict__ Ko,
    int* __restrict__ VPo, unsigned short* __restrict__ Vo)
{
    extern __shared__ int gsm[];   // [2 bufs x 2560] per array: A | B
    int* AsB = gsm;
    int* BsB = gsm + 5120;

    int z = PASS ? 2 : blockIdx.z;
    const int* W = (z == 0) ? wq8 : (z == 1) ? wk8 : wv8;

    int tid = threadIdx.x;
    int m0 = blockIdx.y * 128, n0 = blockIdx.x * 128;
    int w = tid >> 5, lane = tid & 31, g = lane >> 2, t = lane & 3;
    int wm = (w >> 2) * 64, wn = (w & 3) * 32;

    int acc1[4][4][4];
#pragma unroll
    for (int mi = 0; mi < 4; mi++)
#pragma unroll
        for (int ni = 0; ni < 4; ni++)
#pragma unroll
            for (int e = 0; e < 4; e++) acc1[mi][ni][e] = 0;

    int srow = tid >> 1, shalf = (tid & 1) * 8;
    const int* Ag = A8 + (m0 + srow) * 256 + shalf;
    const int* Wg = W  + (n0 + srow) * 256 + shalf;
    int sboff = (srow * 20 + shalf) * 4;

    uint32_t sA = smem_u32(AsB), sB = smem_u32(BsB);

    {
        cp16(sA + sboff, Ag);      cp16(sA + sboff + 16, Ag + 4);
        cp16(sB + sboff, Wg);      cp16(sB + sboff + 16, Wg + 4);
        asm volatile("cp.async.commit_group;");
    }

    for (int ks = 0; ks < 16; ks++) {
        int cur = ks & 1, nxt = cur ^ 1;
        if (ks < 15) {
            uint32_t boff = (uint32_t)nxt * 10240u + (uint32_t)sboff;
            const int* a = Ag + (ks + 1) * 16;
            const int* b = Wg + (ks + 1) * 16;
            cp16(sA + boff, a); cp16(sA + boff + 16, a + 4);
            cp16(sB + boff, b); cp16(sB + boff + 16, b + 4);
            asm volatile("cp.async.commit_group;");
            asm volatile("cp.async.wait_group 1;");
        } else {
            asm volatile("cp.async.wait_group 0;");
        }
        __syncthreads();

        const int* Asw = AsB + cur * 2560;
        const int* Bsw = BsB + cur * 2560;

#pragma unroll
        for (int kk = 0; kk < 2; kk++) {
            int bb0[4], bb1[4];
#pragma unroll
            for (int ni = 0; ni < 4; ni++) {
                int brow = (wn + ni * 8 + g) * 20 + kk * 8;
                bb0[ni] = Bsw[brow + t];
                bb1[ni] = Bsw[brow + 4 + t];
            }
#pragma unroll
            for (int mi = 0; mi < 4; mi++) {
                int ar0 = (wm + mi * 16 + g) * 20 + kk * 8;
                int ar1 = (wm + mi * 16 + 8 + g) * 20 + kk * 8;
                int a0 = Asw[ar0 + t], a1 = Asw[ar1 + t];
                int a2 = Asw[ar0 + 4 + t], a3 = Asw[ar1 + 4 + t];
#pragma unroll
                for (int ni = 0; ni < 4; ni++)
                    imma16832(acc1[mi][ni][0], acc1[mi][ni][1], acc1[mi][ni][2], acc1[mi][ni][3],
                              a0, a1, a2, a3, bb0[ni], bb1[ni]);
            }
        }
        __syncthreads();
    }

    float sa = fmaxf(__uint_as_float(g_absmax[0]), 1e-8f) / 127.0f;
    float sw = fmaxf(__uint_as_float(g_absmax[z + 1]), 1e-8f) / 7.0f;
    float k1 = sa * sw;
    float k2 = (sa / 254.0f) * sw;

#pragma unroll
    for (int mi = 0; mi < 4; mi++) {
        int r0 = m0 + wm + mi * 16 + g;
        int r1 = r0 + 8;
#pragma unroll
        for (int ni = 0; ni < 4; ni++) {
            int c0 = n0 + wn + ni * 8 + 2 * t;
            unsigned i00 = out_idx(r0, c0), i10 = out_idx(r1, c0);
            if (PASS == 0) {
                if (z < 2) {
                    unsigned short* O = (z == 0) ? Qo : Ko;
                    *(unsigned*)&O[i00] = h2w((float)acc1[mi][ni][0] * k1,
                                              (float)acc1[mi][ni][1] * k1);
                    *(unsigned*)&O[i10] = h2w((float)acc1[mi][ni][2] * k1,
                                              (float)acc1[mi][ni][3] * k1);
                } else {
                    // V main term: raw int32 partial
                    *(int2*)&VPo[i00] = make_int2(acc1[mi][ni][0], acc1[mi][ni][1]);
                    *(int2*)&VPo[i10] = make_int2(acc1[mi][ni][2], acc1[mi][ni][3]);
                }
            } else {
                // V residual term: combine with main partial, write fp16
                int2 p0 = *(const int2*)&VPo[i00];
                int2 p1 = *(const int2*)&VPo[i10];
                *(unsigned*)&Vo[i00] = h2w(fmaf((float)acc1[mi][ni][0], k2, (float)p0.x * k1),
                                           fmaf((float)acc1[mi][ni][1], k2, (float)p0.y * k1));
                *(unsigned*)&Vo[i10] = h2w(fmaf((float)acc1[mi][ni][2], k2, (float)p1.x * k1),
                                           fmaf((float)acc1[mi][ni][3], k2, (float)p1.y * k1));
            }
        }
    }
}

// ---------------- JAX threefry2x32 noise (partitionable, key=(0,42)) --------
__device__ __forceinline__ uint32_t rotl32(uint32_t x, int r) {
    return (x << r) | (x >> (32 - r));
}

__device__ __forceinline__ void threefry2x32(uint32_t c0, uint32_t c1,
                                             uint32_t& o0, uint32_t& o1) {
    const uint32_t k0 = 0u, k1 = 42u, k2 = 0u ^ 42u ^ 0x1BD11BDAu;
    uint32_t x0 = c0 + k0, x1 = c1 + k1;
#define TF_R(r) { x0 += x1; x1 = rotl32(x1, r); x1 ^= x0; }
    TF_R(13) TF_R(15) TF_R(26) TF_R(6)
    x0 += k1; x1 += k2 + 1u;
    TF_R(17) TF_R(29) TF_R(16) TF_R(24)
    x0 += k2; x1 += k0 + 2u;
    TF_R(13) TF_R(15) TF_R(26) TF_R(6)
    x0 += k0; x1 += k1 + 3u;
    TF_R(17) TF_R(29) TF_R(16) TF_R(24)
    x0 += k1; x1 += k2 + 4u;
    TF_R(13) TF_R(15) TF_R(26) TF_R(6)
    x0 += k2; x1 += k0 + 5u;
#undef TF_R
    o0 = x0; o1 = x1;
}

__device__ __forceinline__ float noise_at(unsigned int i) {
    uint32_t o0, o1;
    threefry2x32(0u, i, o0, o1);
    uint32_t bits = o0 ^ o1;
    float f = __uint_as_float((bits >> 9) | 0x3f800000u) - 1.0f;
    const float lo = -0.99999994f;
    float u = fmaxf(lo, fmaf(f, 2.0f, lo));
    float t = fmaf(-u, u, 1.0f);
    float w = -__logf(t);
    float p;
    if (w < 5.0f) {
        w = w - 2.5f;
        p = 2.81022636e-08f;
        p = fmaf(p, w, 3.43273939e-07f);
        p = fmaf(p, w, -3.5233877e-06f);
        p = fmaf(p, w, -4.39150654e-06f);
        p = fmaf(p, w, 0.00021858087f);
        p = fmaf(p, w, -0.00125372503f);
        p = fmaf(p, w, -0.00417768164f);
        p = fmaf(p, w, 0.246640727f);
        p = fmaf(p, w, 1.50140941f);
    } else {
        w = sqrtf(w) - 3.0f;
        p = -0.000200214257f;
        p = fmaf(p, w, 0.000100950558f);
        p = fmaf(p, w, 0.00134934322f);
        p = fmaf(p, w, -0.00367342844f);
        p = fmaf(p, w, 0.00573950773f);
        p = fmaf(p, w, -0.0076224613f);
        p = fmaf(p, w, 0.00943887047f);
        p = fmaf(p, w, 1.00167406f);
        p = fmaf(p, w, 2.83297682f);
    }
    return 1.41421356f * (p * u) * 0.05f;
}

// ---------------- HMMA helpers ----------------------------------------------
__device__ __forceinline__ void mma16816(float& c0, float& c1, float& c2, float& c3,
                                         unsigned a0, unsigned a1, unsigned a2, unsigned a3,
                                         unsigned b0, unsigned b1) {
    asm volatile(
        "mma.sync.aligned.m16n8k16.row.col.f32.f16.f16.f32 "
        "{%0,%1,%2,%3},{%4,%5,%6,%7},{%8,%9},{%0,%1,%2,%3};"
        : "+f"(c0), "+f"(c1), "+f"(c2), "+f"(c3)
        : "r"(a0), "r"(a1), "r"(a2), "r"(a3), "r"(b0), "r"(b1));
}

// ---------------- fused flash attention (HMMA, pure fp16 operands) -----------
// Q/K/V fp16; planes as 32-bit words ({d, d+1} half pairs), row stride 36.
// V^T plane [dh][k-pair-word], XOR swizzle col = kp ^ ((dh>>3)&3).
#define PLANEW 2304   // 64 rows * 36 words
__global__ __launch_bounds__(128, 4) void attn_k(
    const unsigned short* __restrict__ Q16, const unsigned short* __restrict__ K16,
    const unsigned short* __restrict__ V16, const float* __restrict__ mask,
    float* __restrict__ out)
{
    extern __shared__ unsigned smw[];
    unsigned* qh_s = smw;
    unsigned* kh_s = smw + PLANEW;
    unsigned* vt_s = smw + 2 * PLANEW;
    float* Ms = (float*)(smw + 3 * PLANEW);

    int bh = blockIdx.x, qt = blockIdx.y;
    int b = bh >> 4, h = bh & 15;
    int tid = threadIdx.x, w = tid >> 5, lane = tid & 31;
    int g = lane >> 2, t = lane & 3;

    const unsigned* Qw = (const unsigned*)(Q16 + (size_t)(bh * 1024 + qt * 64) * 64);
    for (int i = tid; i < 2048; i += 128) {
        int q = i >> 5, dp = i & 31;
        qh_s[q * 36 + dp] = Qw[q * 32 + dp];
    }
    __syncthreads();

    unsigned qh[4][4];
    int qr = w * 16 + g;
#pragma unroll
    for (int c = 0; c < 4; c++) {
        int wp = c * 8 + t;
        qh[c][0] = qh_s[qr * 36 + wp];
        qh[c][1] = qh_s[(qr + 8) * 36 + wp];
        qh[c][2] = qh_s[qr * 36 + wp + 4];
        qh[c][3] = qh_s[(qr + 8) * 36 + wp + 4];
    }

    float m0r = -1e30f, m1r = -1e30f, l0r = 0.f, l1r = 0.f;
    float O[8][4];
#pragma unroll
    for (int n = 0; n < 8; n++)
#pragma unroll
        for (int e = 0; e < 4; e++) O[n][e] = 0.f;

    const float* maskb = mask + (b << 10);
    unsigned base0 = ((unsigned)bh << 20) | ((unsigned)(qt * 64 + qr) << 10);

    for (int kt = 0; kt < 16; kt++) {
        __syncthreads();
        const unsigned* Kw = (const unsigned*)(K16 + (size_t)(bh * 1024 + kt * 64) * 64);
        const unsigned short* Vg = V16 + (size_t)(bh * 1024 + kt * 64) * 64;
        for (int i = tid; i < 2048; i += 128) {
            int k = i >> 5, dp = i & 31;
            kh_s[k * 36 + dp] = Kw[k * 32 + dp];
            int d = i & 63, kp = i >> 6;
            unsigned v0 = Vg[(2 * kp) * 64 + d];
            unsigned v1 = Vg[(2 * kp + 1) * 64 + d];
            int col = kp ^ ((d >> 3) & 3);
            vt_s[d * 36 + col] = v0 | (v1 << 16);
        }
        if (tid < 64) Ms[tid] = maskb[kt * 64 + tid];
        __syncthreads();

        // ---- S = Q K^T (single fp16 term)
        float S[8][4];
#pragma unroll
        for (int n = 0; n < 8; n++)
#pragma unroll
            for (int e = 0; e < 4; e++) S[n][e] = 0.f;

#pragma unroll
        for (int j = 0; j < 8; j++) {
            int krow = j * 8 + g;
#pragma unroll
            for (int c = 0; c < 4; c++) {
                int wp = c * 8 + t;
                unsigned bh0 = kh_s[krow * 36 + wp];
                unsigned bh1 = kh_s[krow * 36 + wp + 4];
                mma16816(S[j][0], S[j][1], S[j][2], S[j][3],
                         qh[c][0], qh[c][1], qh[c][2], qh[c][3], bh0, bh1);
            }
        }

        // ---- scale + noise + mask
#pragma unroll
        for (int j = 0; j < 8; j++) {
            unsigned kc = (unsigned)(kt * 64 + j * 8 + 2 * t);
            float mv0 = Ms[j * 8 + 2 * t], mv1 = Ms[j * 8 + 2 * t + 1];
            S[j][0] = fmaf(S[j][0], 0.125f, noise_at(base0 + kc) + mv0);
            S[j][1] = fmaf(S[j][1], 0.125f, noise_at(base0 + kc + 1) + mv1);
            S[j][2] = fmaf(S[j][2], 0.125f, noise_at(base0 + (8u << 10) + kc) + mv0);
            S[j][3] = fmaf(S[j][3], 0.125f, noise_at(base0 + (8u << 10) + kc + 1) + mv1);
        }

        // ---- online softmax
        float tm0 = -1e30f, tm1 = -1e30f;
#pragma unroll
        for (int j = 0; j < 8; j++) {
            tm0 = fmaxf(tm0, fmaxf(S[j][0], S[j][1]));
            tm1 = fmaxf(tm1, fmaxf(S[j][2], S[j][3]));
        }
        tm0 = fmaxf(tm0, __shfl_xor_sync(0xffffffffu, tm0, 1));
        tm0 = fmaxf(tm0, __shfl_xor_sync(0xffffffffu, tm0, 2));
        tm1 = fmaxf(tm1, __shfl_xor_sync(0xffffffffu, tm1, 1));
        tm1 = fmaxf(tm1, __shfl_xor_sync(0xffffffffu, tm1, 2));
        float mn0 = fmaxf(m0r, tm0), mn1 = fmaxf(m1r, tm1);
        float cor0 = __expf(m0r - mn0), cor1 = __expf(m1r - mn1);
        m0r = mn0; m1r = mn1;
        float ps0 = 0.f, ps1 = 0.f;
#pragma unroll
        for (int j = 0; j < 8; j++) {
            S[j][0] = __expf(S[j][0] - mn0); S[j][1] = __expf(S[j][1] - mn0);
            S[j][2] = __expf(S[j][2] - mn1); S[j][3] = __expf(S[j][3] - mn1);
            ps0 += S[j][0] + S[j][1];
            ps1 += S[j][2] + S[j][3];
        }
        ps0 += __shfl_xor_sync(0xffffffffu, ps0, 1);
        ps0 += __shfl_xor_sync(0xffffffffu, ps0, 2);
        ps1 += __shfl_xor_sync(0xffffffffu, ps1, 1);
        ps1 += __shfl_xor_sync(0xffffffffu, ps1, 2);
        l0r = l0r * cor0 + ps0;
        l1r = l1r * cor1 + ps1;
#pragma unroll
        for (int n = 0; n < 8; n++) {
            O[n][0] *= cor0; O[n][1] *= cor0;
            O[n][2] *= cor1; O[n][3] *= cor1;
        }

        // ---- P -> fp16 A-frags
        unsigned ph[4][4];
#pragma unroll
        for (int c = 0; c < 4; c++) {
            ph[c][0] = h2w(S[2 * c][0],     S[2 * c][1]);
            ph[c][1] = h2w(S[2 * c][2],     S[2 * c][3]);
            ph[c][2] = h2w(S[2 * c + 1][0], S[2 * c + 1][1]);
            ph[c][3] = h2w(S[2 * c + 1][2], S[2 * c + 1][3]);
        }

        // ---- O += P V (single fp16 term; swizzled V^T plane)
#pragma unroll
        for (int n = 0; n < 8; n++) {
            int vrow = n * 8 + g;
            int vs = n & 3;
#pragma unroll
            for (int c = 0; c < 4; c++) {
                int wp0 = (c * 8 + t) ^ vs;
                int wp1 = (c * 8 + 4 + t) ^ vs;
                unsigned bh0 = vt_s[vrow * 36 + wp0];
                unsigned bh1 = vt_s[vrow * 36 + wp1];
                mma16816(O[n][0], O[n][1], O[n][2], O[n][3],
                         ph[c][0], ph[c][1], ph[c][2], ph[c][3], bh0, bh1);
            }
        }
    }

    float inv0 = 1.0f / l0r, inv1 = 1.0f / l1r;
    int q0 = qt * 64 + qr;
    float* o0 = out + ((size_t)((b << 10) + q0)) * 1024 + (h << 6);
    float* o1 = out + ((size_t)((b << 10) + q0 + 8)) * 1024 + (h << 6);
#pragma unroll
    for (int n = 0; n < 8; n++) {
        int dh = n * 8 + 2 * t;
        *(float2*)(o0 + dh) = make_float2(O[n][0] * inv0, O[n][1] * inv0);
        *(float2*)(o1 + dh) = make_float2(O[n][2] * inv1, O[n][3] * inv1);
    }
}

// ---------------- launch -----------------------------------------------------
extern "C" void kernel_launch(void* const* d_in, const int* in_sizes, int n_in,
                              void* d_out, int out_size) {
    const float* hidden = (const float*)d_in[0];
    const float* mask   = (const float*)d_in[1];
    const float* Wq     = (const float*)d_in[2];
    const float* Wk     = (const float*)d_in[3];
    const float* Wv     = (const float*)d_in[4];
    float* out = (float*)d_out;

    int *hq8, *r8, *wq8, *wk8, *wv8, *vp;
    unsigned short *Qp, *Kp, *Vp;
    cudaGetSymbolAddress((void**)&hq8, g_hq8);
    cudaGetSymbolAddress((void**)&r8,  g_r8);
    cudaGetSymbolAddress((void**)&wq8, g_wq8);
    cudaGetSymbolAddress((void**)&wk8, g_wk8);
    cudaGetSymbolAddress((void**)&wv8, g_wv8);
    cudaGetSymbolAddress((void**)&vp,  g_vp);
    cudaGetSymbolAddress((void**)&Qp,  g_Q16);
    cudaGetSymbolAddress((void**)&Kp,  g_K16);
    cudaGetSymbolAddress((void**)&Vp,  g_V16);

    init_k<<<1, 32>>>();
    absmax_all_k<<<dim3(128, 1, 4), 256>>>((const float4*)hidden, (const float4*)Wq,
                                           (const float4*)Wk, (const float4*)Wv);
    pack_all_k<<<dim3(256, 1, 4), 256>>>((const float4*)hidden, (const float4*)Wq,
                                         (const float4*)Wk, (const float4*)Wv,
                                         hq8, r8, wq8, wk8, wv8);

    cudaFuncSetAttribute(gemm_imma<0>, cudaFuncAttributeMaxDynamicSharedMemorySize, 40960);
    cudaFuncSetAttribute(gemm_imma<1>, cudaFuncAttributeMaxDynamicSharedMemorySize, 40960);
    // launch 1: Q, K, V-main(int32 partial)  — all acc1-only, 2 blocks/SM
    gemm_imma<0><<<dim3(8, 32, 3), 256, 40960>>>(hq8, wq8, wk8, wv8, Qp, Kp, vp, Vp);
    // launch 2: V-residual, combines with partial -> fp16 V
    gemm_imma<1><<<dim3(8, 32, 1), 256, 40960>>>(r8, wq8, wk8, wv8, Qp, Kp, vp, Vp);

    int smem_bytes = 3 * PLANEW * 4 + 64 * 4;
    cudaFuncSetAttribute(attn_k, cudaFuncAttributeMaxDynamicSharedMemorySize, smem_bytes);
    attn_k<<<dim3(64, 16), 128, smem_bytes>>>(Qp, Kp, Vp, mask, out);
}